// round 2
// baseline (speedup 1.0000x reference)
#include <cuda_runtime.h>

// Problem dims
#define DM     1792           // D_MODEL
#define BBDIM  256            // BB
#define I_DIM  2048           // inner dim I
#define G_DIM  8192           // 4*I

// Scratch state (allocation-free rule: __device__ globals)
__device__ float g_z[6 * G_DIM];      // gate preactivations (Wih part + both biases)
__device__ float g_h[2][I_DIM];       // ping-pong hidden state
__device__ float g_c[2][I_DIM];       // ping-pong cell state

__device__ __forceinline__ float warp_sum(float v) {
#pragma unroll
    for (int o = 16; o > 0; o >>= 1) v += __shfl_xor_sync(0xffffffffu, v, o);
    return v;
}

__device__ __forceinline__ float sigmoidf(float x) {
    return 1.0f / (1.0f + expf(-x));
}

// ---------------------------------------------------------------------------
// Kernel 1: all input-side matvecs in parallel.
//   t in [0,5): z[t] = Wih5[t] @ concat(x[t], y[t]) + bih5[t] + bhh5[t]
//   t == 5:     z[5] = WihF   @ x[5]                + bihF   + bhhF
// Grid: 6 * 1024 blocks of 256 threads; 8 warps/block, 1 warp per output row.
// ---------------------------------------------------------------------------
__global__ void __launch_bounds__(256) precompute_z(
    const float* __restrict__ x,     // (6, 1792)
    const float* __restrict__ y,     // (5, 256)
    const float* __restrict__ Wih5,  // (5, 8192, 2048)
    const float* __restrict__ bih5,  // (5, 8192)
    const float* __restrict__ bhh5,  // (5, 8192)
    const float* __restrict__ WihF,  // (8192, 1792)
    const float* __restrict__ bihF,  // (8192)
    const float* __restrict__ bhhF)  // (8192)
{
    __shared__ float xs[I_DIM];

    const int t       = blockIdx.x >> 10;          // 1024 blocks per cell
    const int rowBase = (blockIdx.x & 1023) << 3;  // 8 rows per block
    const int tid     = threadIdx.x;

    // Stage the input vector for this cell in shared memory.
    if (t < 5) {
        for (int k = tid; k < DM; k += 256)     xs[k]       = x[t * DM + k];
        for (int k = tid; k < BBDIM; k += 256)  xs[DM + k]  = y[t * BBDIM + k];
    } else {
        for (int k = tid; k < DM; k += 256)     xs[k]       = x[5 * DM + k];
    }
    __syncthreads();

    const int w    = tid >> 5;
    const int lane = tid & 31;
    const int r    = rowBase + w;

    const int len = (t < 5) ? I_DIM : DM;
    const float* rowp = (t < 5)
        ? (Wih5 + ((size_t)t * G_DIM + r) * I_DIM)
        : (WihF + (size_t)r * DM);

    const float4* rp4 = (const float4*)rowp;
    const float4* xs4 = (const float4*)xs;
    const int nv = len >> 2;                        // 512 or 448 float4s

    float acc = 0.0f;
#pragma unroll 4
    for (int k = lane; k < nv; k += 32) {
        float4 a = rp4[k];
        float4 b = xs4[k];
        acc += a.x * b.x + a.y * b.y + a.z * b.z + a.w * b.w;
    }
    acc = warp_sum(acc);

    if (lane == 0) {
        float bias = (t < 5)
            ? (bih5[(size_t)t * G_DIM + r] + bhh5[(size_t)t * G_DIM + r])
            : (bihF[r] + bhhF[r]);
        g_z[(size_t)t * G_DIM + r] = acc + bias;
    }
}

// ---------------------------------------------------------------------------
// Kernel 2: step 0. h0 = c0 = 0, so Whh contributes nothing and f*c0 = 0.
//   c = sigmoid(z_i) * tanh(z_g);  h = sigmoid(z_o) * tanh(c)
// ---------------------------------------------------------------------------
__global__ void step0_kernel() {
    int j = blockIdx.x * blockDim.x + threadIdx.x;
    if (j >= I_DIM) return;
    float zi = g_z[j];
    float zg = g_z[2 * I_DIM + j];
    float zo = g_z[3 * I_DIM + j];
    float c  = sigmoidf(zi) * tanhf(zg);
    float h  = sigmoidf(zo) * tanhf(c);
    g_c[0][j] = c;
    g_h[0][j] = h;
}

// ---------------------------------------------------------------------------
// Kernel 3: recurrent step (steps 1..4 with Whh5[t], final step with WhhF).
// Each block handles 2 output elements j; for each j, 4 warps compute the
// 4 gate-row dot products Whh[gate*2048 + j, :] @ h_prev, then the gate math
// fuses in-block — no extra global sync.
// ---------------------------------------------------------------------------
__global__ void __launch_bounds__(256) step_rec(
    const float* __restrict__ whh,   // (8192, 2048) row-major
    int zoff, int pin, int pout,
    float* __restrict__ out)         // d_out for the final step, else null
{
    __shared__ float hs[I_DIM];
    __shared__ float dots[8];

    const int tid = threadIdx.x;
    for (int k = tid; k < I_DIM; k += 256) hs[k] = g_h[pin][k];
    __syncthreads();

    const int w    = tid >> 5;
    const int lane = tid & 31;
    const int j    = (blockIdx.x << 1) + (w >> 2);
    const int gate = w & 3;
    const int row  = gate * I_DIM + j;

    const float4* rp4 = (const float4*)(whh + (size_t)row * I_DIM);
    const float4* hs4 = (const float4*)hs;

    float acc = 0.0f;
#pragma unroll 4
    for (int k = lane; k < (I_DIM >> 2); k += 32) {
        float4 a = rp4[k];
        float4 b = hs4[k];
        acc += a.x * b.x + a.y * b.y + a.z * b.z + a.w * b.w;
    }
    acc = warp_sum(acc);
    if (lane == 0) dots[w] = acc;
    __syncthreads();

    if (tid < 2) {
        const int jj = (blockIdx.x << 1) + tid;
        const float* z = g_z + zoff;
        float gi = z[jj]             + dots[tid * 4 + 0];
        float gf = z[I_DIM + jj]     + dots[tid * 4 + 1];
        float gg = z[2 * I_DIM + jj] + dots[tid * 4 + 2];
        float go = z[3 * I_DIM + jj] + dots[tid * 4 + 3];
        float c  = sigmoidf(gf) * g_c[pin][jj] + sigmoidf(gi) * tanhf(gg);
        float h  = sigmoidf(go) * tanhf(c);
        g_c[pout][jj] = c;
        g_h[pout][jj] = h;
        if (out != nullptr && jj >= DM) out[jj - DM] = h;
    }
}

// ---------------------------------------------------------------------------
extern "C" void kernel_launch(void* const* d_in, const int* in_sizes, int n_in,
                              void* d_out, int out_size)
{
    const float* x    = (const float*)d_in[0];
    const float* y    = (const float*)d_in[1];
    const float* Wih5 = (const float*)d_in[2];
    const float* Whh5 = (const float*)d_in[3];
    const float* bih5 = (const float*)d_in[4];
    const float* bhh5 = (const float*)d_in[5];
    const float* WihF = (const float*)d_in[6];
    const float* WhhF = (const float*)d_in[7];
    const float* bihF = (const float*)d_in[8];
    const float* bhhF = (const float*)d_in[9];
    float* out = (float*)d_out;

    (void)in_sizes; (void)n_in; (void)out_size;

    // 1) all 6 input-side matvecs in parallel (394 MB streamed)
    precompute_z<<<6 * 1024, 256>>>(x, y, Wih5, bih5, bhh5, WihF, bihF, bhhF);

    // 2) step 0: h0 = c0 = 0 -> no Whh read at all
    step0_kernel<<<(I_DIM + 255) / 256, 256>>>();

    // 3) steps 1..4: sequential Whh matvecs (67 MB each)
    int pin = 0;
    for (int t = 1; t <= 4; ++t) {
        step_rec<<<1024, 256>>>(Whh5 + (size_t)t * G_DIM * I_DIM,
                                t * G_DIM, pin, 1 - pin, nullptr);
        pin = 1 - pin;
    }

    // 4) final cell with WhhF; writes h[1792:2048] straight to d_out
    step_rec<<<1024, 256>>>(WhhF, 5 * G_DIM, pin, 1 - pin, out);
}

// round 3
// speedup vs baseline: 1.1788x; 1.1788x over previous
#include <cuda_runtime.h>

// Problem dims
#define DM     1792           // D_MODEL
#define BBDIM  256            // BB
#define I_DIM  2048           // inner dim I
#define G_DIM  8192           // 4*I

// Scratch state (allocation-free rule: __device__ globals)
__device__ float g_z[6 * G_DIM];      // gate preactivations (Wih part + both biases)
__device__ float g_h[2][I_DIM];       // ping-pong hidden state
__device__ float g_c[2][I_DIM];       // ping-pong cell state

__device__ __forceinline__ float warp_sum(float v) {
#pragma unroll
    for (int o = 16; o > 0; o >>= 1) v += __shfl_xor_sync(0xffffffffu, v, o);
    return v;
}

__device__ __forceinline__ float sigmoidf_(float x) {
    return 1.0f / (1.0f + expf(-x));
}

__device__ __forceinline__ float dot4(float4 a, float4 b) {
    return a.x * b.x + a.y * b.y + a.z * b.z + a.w * b.w;
}

// Streaming load of a float4 (evict-first: weights are touched exactly once)
__device__ __forceinline__ float4 ldcs4(const float4* p) {
    return __ldcs(p);
}

// ---------------------------------------------------------------------------
// Warp-level row dot product with full unroll: NITER independent LDG.128 in
// flight per warp, 4 independent accumulators. NITER is a compile-time
// constant so the loop fully unrolls.
// ---------------------------------------------------------------------------
template <int NITER>
__device__ __forceinline__ float row_dot(const float4* __restrict__ rp4,
                                         const float4* __restrict__ v4,
                                         int lane)
{
    float a0 = 0.f, a1 = 0.f, a2 = 0.f, a3 = 0.f;
#pragma unroll
    for (int i = 0; i < NITER; i += 4) {
        float4 w0 = ldcs4(rp4 + lane + (i + 0) * 32);
        float4 w1 = ldcs4(rp4 + lane + (i + 1) * 32);
        float4 w2 = ldcs4(rp4 + lane + (i + 2) * 32);
        float4 w3 = ldcs4(rp4 + lane + (i + 3) * 32);
        float4 h0 = v4[lane + (i + 0) * 32];
        float4 h1 = v4[lane + (i + 1) * 32];
        float4 h2 = v4[lane + (i + 2) * 32];
        float4 h3 = v4[lane + (i + 3) * 32];
        a0 += dot4(w0, h0);
        a1 += dot4(w1, h1);
        a2 += dot4(w2, h2);
        a3 += dot4(w3, h3);
    }
    return (a0 + a1) + (a2 + a3);
}

// ---------------------------------------------------------------------------
// Kernel 1a: input-side matvecs for cells 0..4 (K = 2048, 16 float4 iters).
//   z[t] = Wih5[t] @ concat(x[t], y[t]) + bih5[t] + bhh5[t]
// Grid: 5 * 1024 blocks of 256 threads; 8 warps/block, 1 warp per output row.
// ---------------------------------------------------------------------------
__global__ void __launch_bounds__(256) precompute_z5(
    const float* __restrict__ x,     // (6, 1792)
    const float* __restrict__ y,     // (5, 256)
    const float* __restrict__ Wih5,  // (5, 8192, 2048)
    const float* __restrict__ bih5,  // (5, 8192)
    const float* __restrict__ bhh5)  // (5, 8192)
{
    __shared__ float xs[I_DIM];

    const int t       = blockIdx.x >> 10;          // 1024 blocks per cell
    const int rowBase = (blockIdx.x & 1023) << 3;  // 8 rows per block
    const int tid     = threadIdx.x;

    for (int k = tid; k < DM; k += 256)    xs[k]      = x[t * DM + k];
    for (int k = tid; k < BBDIM; k += 256) xs[DM + k] = y[t * BBDIM + k];
    __syncthreads();

    const int w    = tid >> 5;
    const int lane = tid & 31;
    const int r    = rowBase + w;

    const float4* rp4 = (const float4*)(Wih5 + ((size_t)t * G_DIM + r) * I_DIM);
    const float4* xs4 = (const float4*)xs;

    float acc = row_dot<16>(rp4, xs4, lane);       // 2048/4/32 = 16
    acc = warp_sum(acc);

    if (lane == 0) {
        g_z[(size_t)t * G_DIM + r] =
            acc + bih5[(size_t)t * G_DIM + r] + bhh5[(size_t)t * G_DIM + r];
    }
}

// ---------------------------------------------------------------------------
// Kernel 1b: input-side matvec for the final cell (K = 1792, 14 float4 iters,
// but 14 % 4 != 0 so use 12 unrolled + 2 tail folded in).
//   z[5] = WihF @ x[5] + bihF + bhhF
// ---------------------------------------------------------------------------
__global__ void __launch_bounds__(256) precompute_zF(
    const float* __restrict__ x,     // (6, 1792)
    const float* __restrict__ WihF,  // (8192, 1792)
    const float* __restrict__ bihF,  // (8192)
    const float* __restrict__ bhhF)  // (8192)
{
    __shared__ float xs[DM];

    const int rowBase = blockIdx.x << 3;
    const int tid     = threadIdx.x;

    for (int k = tid; k < DM; k += 256) xs[k] = x[5 * DM + k];
    __syncthreads();

    const int w    = tid >> 5;
    const int lane = tid & 31;
    const int r    = rowBase + w;

    const float4* rp4 = (const float4*)(WihF + (size_t)r * DM);
    const float4* xs4 = (const float4*)xs;

    // 1792/4 = 448 float4 = 14 iterations of 32 lanes. Unroll all 14.
    float a0 = 0.f, a1 = 0.f;
#pragma unroll
    for (int i = 0; i < 14; i += 2) {
        float4 w0 = ldcs4(rp4 + lane + (i + 0) * 32);
        float4 w1 = ldcs4(rp4 + lane + (i + 1) * 32);
        float4 h0 = xs4[lane + (i + 0) * 32];
        float4 h1 = xs4[lane + (i + 1) * 32];
        a0 += dot4(w0, h0);
        a1 += dot4(w1, h1);
    }
    float acc = warp_sum(a0 + a1);

    if (lane == 0) {
        g_z[(size_t)5 * G_DIM + r] = acc + bihF[r] + bhhF[r];
    }
}

// ---------------------------------------------------------------------------
// Kernel 2: step 0. h0 = c0 = 0, so Whh contributes nothing and f*c0 = 0.
// ---------------------------------------------------------------------------
__global__ void step0_kernel() {
    int j = blockIdx.x * blockDim.x + threadIdx.x;
    if (j >= I_DIM) return;
    float zi = g_z[j];
    float zg = g_z[2 * I_DIM + j];
    float zo = g_z[3 * I_DIM + j];
    float c  = sigmoidf_(zi) * tanhf(zg);
    float h  = sigmoidf_(zo) * tanhf(c);
    g_c[0][j] = c;
    g_h[0][j] = h;
}

// ---------------------------------------------------------------------------
// Kernel 3: recurrent step. 2048 blocks x 128 threads: block = one output
// element j; warp w computes gate row w*2048 + j. Full-unroll dot (16 LDG.128
// in flight per warp), gate math fused in-block.
// ---------------------------------------------------------------------------
__global__ void __launch_bounds__(128) step_rec(
    const float* __restrict__ whh,   // (8192, 2048) row-major
    int zoff, int pin, int pout,
    float* __restrict__ out)         // d_out for the final step, else null
{
    __shared__ float hs[I_DIM];
    __shared__ float dots[4];

    const int tid = threadIdx.x;

    // Stage h_prev (8 KB) via float4
    {
        const float4* gh4 = (const float4*)g_h[pin];
        float4* s4 = (float4*)hs;
#pragma unroll
        for (int k = 0; k < 4; ++k) s4[tid + k * 128] = gh4[tid + k * 128];
    }
    __syncthreads();

    const int w    = tid >> 5;
    const int lane = tid & 31;
    const int j    = blockIdx.x;

    const float4* rp4 = (const float4*)(whh + ((size_t)w * I_DIM + j) * I_DIM);
    const float4* hs4 = (const float4*)hs;

    float acc = row_dot<16>(rp4, hs4, lane);
    acc = warp_sum(acc);
    if (lane == 0) dots[w] = acc;
    __syncthreads();

    if (tid == 0) {
        const float* z = g_z + zoff;
        float gi = z[j]             + dots[0];
        float gf = z[I_DIM + j]     + dots[1];
        float gg = z[2 * I_DIM + j] + dots[2];
        float go = z[3 * I_DIM + j] + dots[3];
        float c  = sigmoidf_(gf) * g_c[pin][j] + sigmoidf_(gi) * tanhf(gg);
        float h  = sigmoidf_(go) * tanhf(c);
        g_c[pout][j] = c;
        g_h[pout][j] = h;
        if (out != nullptr && j >= DM) out[j - DM] = h;
    }
}

// ---------------------------------------------------------------------------
extern "C" void kernel_launch(void* const* d_in, const int* in_sizes, int n_in,
                              void* d_out, int out_size)
{
    const float* x    = (const float*)d_in[0];
    const float* y    = (const float*)d_in[1];
    const float* Wih5 = (const float*)d_in[2];
    const float* Whh5 = (const float*)d_in[3];
    const float* bih5 = (const float*)d_in[4];
    const float* bhh5 = (const float*)d_in[5];
    const float* WihF = (const float*)d_in[6];
    const float* WhhF = (const float*)d_in[7];
    const float* bihF = (const float*)d_in[8];
    const float* bhhF = (const float*)d_in[9];
    float* out = (float*)d_out;

    (void)in_sizes; (void)n_in; (void)out_size;

    // 1) all 6 input-side matvecs (394 MB streamed, fully parallel)
    precompute_z5<<<5 * 1024, 256>>>(x, y, Wih5, bih5, bhh5);
    precompute_zF<<<1024, 256>>>(x, WihF, bihF, bhhF);

    // 2) step 0: h0 = c0 = 0 -> no Whh read at all (skips Whh5[0], 67 MB)
    step0_kernel<<<(I_DIM + 255) / 256, 256>>>();

    // 3) steps 1..4: sequential Whh matvecs (67 MB each)
    int pin = 0;
    for (int t = 1; t <= 4; ++t) {
        step_rec<<<I_DIM, 128>>>(Whh5 + (size_t)t * G_DIM * I_DIM,
                                 t * G_DIM, pin, 1 - pin, nullptr);
        pin = 1 - pin;
    }

    // 4) final cell with WhhF; writes h[1792:2048] straight to d_out
    step_rec<<<I_DIM, 128>>>(WhhF, 5 * G_DIM, pin, 1 - pin, out);
}

// round 4
// speedup vs baseline: 1.1970x; 1.0154x over previous
#include <cuda_runtime.h>

// Problem dims
#define DM     1792           // D_MODEL
#define BBDIM  256            // BB
#define I_DIM  2048           // inner dim I
#define G_DIM  8192           // 4*I
#define STEP_BLOCKS 2048      // one block per output j in the recurrent part

// Scratch state (allocation-free rule: __device__ globals)
__device__ float g_z[6 * G_DIM];      // gate preactivations (Wih part + both biases)
__device__ float g_h[2][I_DIM];       // ping-pong hidden state
__device__ float g_c[2][I_DIM];       // ping-pong cell state

__device__ __forceinline__ float warp_sum(float v) {
#pragma unroll
    for (int o = 16; o > 0; o >>= 1) v += __shfl_xor_sync(0xffffffffu, v, o);
    return v;
}

__device__ __forceinline__ float sigmoidf_(float x) {
    return 1.0f / (1.0f + expf(-x));
}

__device__ __forceinline__ float dot4(float4 a, float4 b) {
    return a.x * b.x + a.y * b.y + a.z * b.z + a.w * b.w;
}

// ---------------------------------------------------------------------------
// Two-phase warp dot product: issue ALL weight loads first (keeps NITER
// LDG.128 in flight per warp), then FMA against the smem vector.
// ---------------------------------------------------------------------------
template <int NITER>
__device__ __forceinline__ float row_dot(const float4* __restrict__ rp4,
                                         const float4* __restrict__ v4,
                                         int lane)
{
    float4 w[NITER];
#pragma unroll
    for (int i = 0; i < NITER; ++i) w[i] = __ldcs(rp4 + lane + i * 32);

    float acc[4] = {0.f, 0.f, 0.f, 0.f};
#pragma unroll
    for (int i = 0; i < NITER; ++i) {
        float4 h = v4[lane + i * 32];
        acc[i & 3] += dot4(w[i], h);
    }
    return (acc[0] + acc[1]) + (acc[2] + acc[3]);
}

// ---------------------------------------------------------------------------
// K0: input-side matvecs for cells 0 and 1 (K = 2048).
//   z[t] = Wih5[t] @ concat(x[t], y[t]) + bih5[t] + bhh5[t]
// Grid: 2 * 1024 blocks of 256 threads; 8 warps/block, 1 warp per output row.
// ---------------------------------------------------------------------------
__global__ void __launch_bounds__(256, 2) precompute_z01(
    const float* __restrict__ x,     // (6, 1792)
    const float* __restrict__ y,     // (5, 256)
    const float* __restrict__ Wih5,  // (5, 8192, 2048)
    const float* __restrict__ bih5,  // (5, 8192)
    const float* __restrict__ bhh5)  // (5, 8192)
{
    __shared__ float xs[I_DIM];

    const int t       = blockIdx.x >> 10;          // cell 0 or 1
    const int rowBase = (blockIdx.x & 1023) << 3;  // 8 rows per block
    const int tid     = threadIdx.x;

    for (int k = tid; k < DM; k += 256)    xs[k]      = x[t * DM + k];
    for (int k = tid; k < BBDIM; k += 256) xs[DM + k] = y[t * BBDIM + k];
    __syncthreads();

    const int w    = tid >> 5;
    const int lane = tid & 31;
    const int r    = rowBase + w;

    const float4* rp4 = (const float4*)(Wih5 + ((size_t)t * G_DIM + r) * I_DIM);
    const float4* xs4 = (const float4*)xs;

    float acc = warp_sum(row_dot<16>(rp4, xs4, lane));
    if (lane == 0) {
        g_z[(size_t)t * G_DIM + r] =
            acc + bih5[(size_t)t * G_DIM + r] + bhh5[(size_t)t * G_DIM + r];
    }
}

// ---------------------------------------------------------------------------
// step 0: h0 = c0 = 0 -> Whh contributes nothing, f*c0 = 0. (skips Whh5[0])
// ---------------------------------------------------------------------------
__global__ void step0_kernel() {
    int j = blockIdx.x * blockDim.x + threadIdx.x;
    if (j >= I_DIM) return;
    float zi = g_z[j];
    float zg = g_z[2 * I_DIM + j];
    float zo = g_z[3 * I_DIM + j];
    float c  = sigmoidf_(zi) * tanhf(zg);
    float h  = sigmoidf_(zo) * tanhf(c);
    g_c[0][j] = c;
    g_h[0][j] = h;
}

// ---------------------------------------------------------------------------
// Fused kernel: blocks [0, 2048) do recurrent step t; blocks >= 2048 do the
// z-precompute for the NEXT cell in the same launch (overlaps the
// latency-bound recurrent chain with parallel streaming work, single stream).
//
// mode 0: z part = full cell t+1 (Wih5[t+1], K=2048, 8192 rows, 2048 z-blocks)
// mode 1: z part = final-cell SLICE (WihF rows g*2048+[1792,2048), K=1792,
//         1024 rows, 256 z-blocks)  -- only h[-256:] is ever needed.
// ---------------------------------------------------------------------------
__global__ void __launch_bounds__(128, 4) fused_step(
    const float* __restrict__ whh,   // (8192, 2048) Whh for step t
    int zoff, int pin, int pout,
    const float* __restrict__ wz,    // Wih for next cell
    const float* __restrict__ xvec,  // x row for next cell
    const float* __restrict__ yvec,  // y row for next cell (null in mode 1)
    const float* __restrict__ bih,   // bih for next cell
    const float* __restrict__ bhh,   // bhh for next cell
    int zout, int mode)
{
    __shared__ float sbuf[I_DIM];
    __shared__ float dots[4];

    const int tid  = threadIdx.x;
    const int w    = tid >> 5;
    const int lane = tid & 31;

    if (blockIdx.x < STEP_BLOCKS) {
        // ---------------- recurrent step role ----------------
        {
            const float4* gh4 = (const float4*)g_h[pin];
            float4* s4 = (float4*)sbuf;
#pragma unroll
            for (int k = 0; k < 4; ++k) s4[tid + k * 128] = gh4[tid + k * 128];
        }
        __syncthreads();

        const int j = blockIdx.x;
        const float4* rp4 = (const float4*)(whh + ((size_t)w * I_DIM + j) * I_DIM);
        float acc = warp_sum(row_dot<16>(rp4, (const float4*)sbuf, lane));
        if (lane == 0) dots[w] = acc;
        __syncthreads();

        if (tid == 0) {
            const float* z = g_z + zoff;
            float gi = z[j]             + dots[0];
            float gf = z[I_DIM + j]     + dots[1];
            float gg = z[2 * I_DIM + j] + dots[2];
            float go = z[3 * I_DIM + j] + dots[3];
            float c  = sigmoidf_(gf) * g_c[pin][j] + sigmoidf_(gi) * tanhf(gg);
            float h  = sigmoidf_(go) * tanhf(c);
            g_c[pout][j] = c;
            g_h[pout][j] = h;
        }
    } else {
        // ---------------- z-precompute role ----------------
        const int zb = blockIdx.x - STEP_BLOCKS;

        if (mode == 0) {
            for (int k = tid; k < DM; k += 128)    sbuf[k]      = xvec[k];
            for (int k = tid; k < BBDIM; k += 128) sbuf[DM + k] = yvec[k];
            __syncthreads();

            const int r = (zb << 2) + w;           // 4 rows per block
            const float4* rp4 = (const float4*)(wz + (size_t)r * I_DIM);
            float acc = warp_sum(row_dot<16>(rp4, (const float4*)sbuf, lane));
            if (lane == 0) g_z[zout + r] = acc + bih[r] + bhh[r];
        } else {
            for (int k = tid; k < DM; k += 128) sbuf[k] = xvec[k];
            __syncthreads();

            const int rl = (zb << 2) + w;          // 0..1023
            const int g  = rl >> 8;
            const int jj = rl & 255;
            const int r  = g * I_DIM + DM + jj;    // actual WihF / z row
            const float4* rp4 = (const float4*)(wz + (size_t)r * DM);
            float acc = warp_sum(row_dot<14>(rp4, (const float4*)sbuf, lane));
            if (lane == 0) g_z[zout + r] = acc + bih[r] + bhh[r];
        }
    }
}

// ---------------------------------------------------------------------------
// Final step: only j in [1792, 2048) is needed. 256 blocks, one j each;
// warp w computes gate row w*2048 + j of WhhF. Writes d_out directly.
// ---------------------------------------------------------------------------
__global__ void __launch_bounds__(128, 4) final_step(
    const float* __restrict__ whhF,  // (8192, 2048)
    int pin,
    float* __restrict__ out)
{
    __shared__ float hs[I_DIM];
    __shared__ float dots[4];

    const int tid  = threadIdx.x;
    const int w    = tid >> 5;
    const int lane = tid & 31;

    {
        const float4* gh4 = (const float4*)g_h[pin];
        float4* s4 = (float4*)hs;
#pragma unroll
        for (int k = 0; k < 4; ++k) s4[tid + k * 128] = gh4[tid + k * 128];
    }
    __syncthreads();

    const int j = DM + blockIdx.x;                 // 1792 .. 2047
    const float4* rp4 = (const float4*)(whhF + ((size_t)w * I_DIM + j) * I_DIM);
    float acc = warp_sum(row_dot<16>(rp4, (const float4*)hs, lane));
    if (lane == 0) dots[w] = acc;
    __syncthreads();

    if (tid == 0) {
        const float* z = g_z + 5 * G_DIM;
        float gi = z[j]             + dots[0];
        float gf = z[I_DIM + j]     + dots[1];
        float gg = z[2 * I_DIM + j] + dots[2];
        float go = z[3 * I_DIM + j] + dots[3];
        float c  = sigmoidf_(gf) * g_c[pin][j] + sigmoidf_(gi) * tanhf(gg);
        float h  = sigmoidf_(go) * tanhf(c);
        out[blockIdx.x] = h;
    }
}

// ---------------------------------------------------------------------------
extern "C" void kernel_launch(void* const* d_in, const int* in_sizes, int n_in,
                              void* d_out, int out_size)
{
    const float* x    = (const float*)d_in[0];
    const float* y    = (const float*)d_in[1];
    const float* Wih5 = (const float*)d_in[2];
    const float* Whh5 = (const float*)d_in[3];
    const float* bih5 = (const float*)d_in[4];
    const float* bhh5 = (const float*)d_in[5];
    const float* WihF = (const float*)d_in[6];
    const float* WhhF = (const float*)d_in[7];
    const float* bihF = (const float*)d_in[8];
    const float* bhhF = (const float*)d_in[9];
    float* out = (float*)d_out;

    (void)in_sizes; (void)n_in; (void)out_size;

    const size_t WSTEP = (size_t)G_DIM * I_DIM;    // elems per (8192,2048) matrix

    // K0: z[0] and z[1] (134 MB, fully parallel)
    precompute_z01<<<2048, 256>>>(x, y, Wih5, bih5, bhh5);

    // step 0 (h0=c0=0: no Whh read)
    step0_kernel<<<(I_DIM + 255) / 256, 256>>>();

    // S1..S3: step t fused with z-precompute for cell t+1 (134 MB each)
    int pin = 0;
    for (int t = 1; t <= 3; ++t) {
        fused_step<<<STEP_BLOCKS + 2048, 128>>>(
            Whh5 + (size_t)t * WSTEP, t * G_DIM, pin, 1 - pin,
            Wih5 + (size_t)(t + 1) * WSTEP,
            x + (t + 1) * DM, y + (t + 1) * BBDIM,
            bih5 + (size_t)(t + 1) * G_DIM, bhh5 + (size_t)(t + 1) * G_DIM,
            (t + 1) * G_DIM, /*mode=*/0);
        pin = 1 - pin;
    }

    // S4: step 4 fused with the FINAL-cell z slice (67 + 7.3 MB)
    fused_step<<<STEP_BLOCKS + 256, 128>>>(
        Whh5 + (size_t)4 * WSTEP, 4 * G_DIM, pin, 1 - pin,
        WihF, x + 5 * DM, nullptr,
        bihF, bhhF, 5 * G_DIM, /*mode=*/1);
    pin = 1 - pin;

    // S5: final step, sliced to the 256 needed outputs (8.4 MB)
    final_step<<<256, 128>>>(WhhF, pin, out);
}

// round 5
// speedup vs baseline: 1.2748x; 1.0651x over previous
#include <cuda_runtime.h>

// Problem dims
#define DM     1792           // D_MODEL
#define BBDIM  256            // BB
#define I_DIM  2048           // inner dim I
#define G_DIM  8192           // 4*I
#define STEP_BLOCKS 2048      // one block per output j in the recurrent part

// Scratch state (allocation-free rule: __device__ globals)
__device__ float g_z[6 * G_DIM];      // gate preactivations (Wih part + both biases)
__device__ float g_h[2][I_DIM];       // ping-pong hidden state
__device__ float g_c[2][I_DIM];       // ping-pong cell state

__device__ __forceinline__ float warp_sum(float v) {
#pragma unroll
    for (int o = 16; o > 0; o >>= 1) v += __shfl_xor_sync(0xffffffffu, v, o);
    return v;
}

__device__ __forceinline__ float sigmoidf_(float x) {
    return 1.0f / (1.0f + expf(-x));
}

__device__ __forceinline__ float dot4(float4 a, float4 b) {
    return a.x * b.x + a.y * b.y + a.z * b.z + a.w * b.w;
}

// ---------------------------------------------------------------------------
// Software-pipelined, double-buffered warp dot product over K = 2048
// (16 float4 per lane, 4 chunks of 4). While chunk c is being FMA'd, chunk
// c+1 is already in flight -> sustained 4-8 LDG.128 per warp, ~50 regs.
// ---------------------------------------------------------------------------
__device__ __forceinline__ float row_dot16_pipe(const float4* __restrict__ rp4,
                                                const float4* __restrict__ v4,
                                                int lane)
{
    float4 A[4], B[4];
    float acc[4] = {0.f, 0.f, 0.f, 0.f};

#pragma unroll
    for (int u = 0; u < 4; ++u) A[u] = __ldcs(rp4 + lane + u * 32);          // c0

#pragma unroll
    for (int u = 0; u < 4; ++u) B[u] = __ldcs(rp4 + lane + (4 + u) * 32);    // c1
#pragma unroll
    for (int u = 0; u < 4; ++u) acc[u] += dot4(A[u], v4[lane + u * 32]);     // fma c0

#pragma unroll
    for (int u = 0; u < 4; ++u) A[u] = __ldcs(rp4 + lane + (8 + u) * 32);    // c2
#pragma unroll
    for (int u = 0; u < 4; ++u) acc[u] += dot4(B[u], v4[lane + (4 + u) * 32]); // fma c1

#pragma unroll
    for (int u = 0; u < 4; ++u) B[u] = __ldcs(rp4 + lane + (12 + u) * 32);   // c3
#pragma unroll
    for (int u = 0; u < 4; ++u) acc[u] += dot4(A[u], v4[lane + (8 + u) * 32]); // fma c2

#pragma unroll
    for (int u = 0; u < 4; ++u) acc[u] += dot4(B[u], v4[lane + (12 + u) * 32]); // fma c3

    return (acc[0] + acc[1]) + (acc[2] + acc[3]);
}

// Same, for K = 1792 (14 float4 per lane: chunks 4,4,4,2).
__device__ __forceinline__ float row_dot14_pipe(const float4* __restrict__ rp4,
                                                const float4* __restrict__ v4,
                                                int lane)
{
    float4 A[4], B[4];
    float acc[4] = {0.f, 0.f, 0.f, 0.f};

#pragma unroll
    for (int u = 0; u < 4; ++u) A[u] = __ldcs(rp4 + lane + u * 32);

#pragma unroll
    for (int u = 0; u < 4; ++u) B[u] = __ldcs(rp4 + lane + (4 + u) * 32);
#pragma unroll
    for (int u = 0; u < 4; ++u) acc[u] += dot4(A[u], v4[lane + u * 32]);

#pragma unroll
    for (int u = 0; u < 4; ++u) A[u] = __ldcs(rp4 + lane + (8 + u) * 32);
#pragma unroll
    for (int u = 0; u < 4; ++u) acc[u] += dot4(B[u], v4[lane + (4 + u) * 32]);

#pragma unroll
    for (int u = 0; u < 2; ++u) B[u] = __ldcs(rp4 + lane + (12 + u) * 32);
#pragma unroll
    for (int u = 0; u < 4; ++u) acc[u] += dot4(A[u], v4[lane + (8 + u) * 32]);

#pragma unroll
    for (int u = 0; u < 2; ++u) acc[u] += dot4(B[u], v4[lane + (12 + u) * 32]);

    return (acc[0] + acc[1]) + (acc[2] + acc[3]);
}

// ---------------------------------------------------------------------------
// K0: input-side matvecs for cells 0 and 1 (K = 2048).
// Grid: 2 * 1024 blocks of 256 threads; 8 warps/block, 1 warp per output row.
// ---------------------------------------------------------------------------
__global__ void __launch_bounds__(256, 4) precompute_z01(
    const float* __restrict__ x,     // (6, 1792)
    const float* __restrict__ y,     // (5, 256)
    const float* __restrict__ Wih5,  // (5, 8192, 2048)
    const float* __restrict__ bih5,  // (5, 8192)
    const float* __restrict__ bhh5)  // (5, 8192)
{
    __shared__ float xs[I_DIM];

    const int t       = blockIdx.x >> 10;          // cell 0 or 1
    const int rowBase = (blockIdx.x & 1023) << 3;  // 8 rows per block
    const int tid     = threadIdx.x;

    for (int k = tid; k < DM; k += 256)    xs[k]      = x[t * DM + k];
    for (int k = tid; k < BBDIM; k += 256) xs[DM + k] = y[t * BBDIM + k];
    __syncthreads();

    const int w    = tid >> 5;
    const int lane = tid & 31;
    const int r    = rowBase + w;

    const float4* rp4 = (const float4*)(Wih5 + ((size_t)t * G_DIM + r) * I_DIM);
    float acc = warp_sum(row_dot16_pipe(rp4, (const float4*)xs, lane));
    if (lane == 0) {
        g_z[(size_t)t * G_DIM + r] =
            acc + bih5[(size_t)t * G_DIM + r] + bhh5[(size_t)t * G_DIM + r];
    }
}

// ---------------------------------------------------------------------------
// step 0: h0 = c0 = 0 -> Whh contributes nothing, f*c0 = 0. (skips Whh5[0])
// ---------------------------------------------------------------------------
__global__ void step0_kernel() {
    int j = blockIdx.x * blockDim.x + threadIdx.x;
    if (j >= I_DIM) return;
    float zi = g_z[j];
    float zg = g_z[2 * I_DIM + j];
    float zo = g_z[3 * I_DIM + j];
    float c  = sigmoidf_(zi) * tanhf(zg);
    float h  = sigmoidf_(zo) * tanhf(c);
    g_c[0][j] = c;
    g_h[0][j] = h;
}

// ---------------------------------------------------------------------------
// Fused kernel: blocks [0, 2048) do recurrent step t; blocks >= 2048 do the
// z-precompute for the NEXT cell in the same launch.
//
// mode 0: z part = full cell t+1 (Wih5[t+1], K=2048, 8192 rows, 2048 z-blocks)
// mode 1: z part = final-cell SLICE (WihF rows g*2048+[1792,2048), K=1792,
//         1024 rows, 256 z-blocks)  -- only h[-256:] is ever needed.
// ---------------------------------------------------------------------------
__global__ void __launch_bounds__(128, 8) fused_step(
    const float* __restrict__ whh,   // (8192, 2048) Whh for step t
    int zoff, int pin, int pout,
    const float* __restrict__ wz,    // Wih for next cell
    const float* __restrict__ xvec,  // x row for next cell
    const float* __restrict__ yvec,  // y row for next cell (null in mode 1)
    const float* __restrict__ bih,   // bih for next cell
    const float* __restrict__ bhh,   // bhh for next cell
    int zout, int mode)
{
    __shared__ float sbuf[I_DIM];
    __shared__ float dots[4];

    const int tid  = threadIdx.x;
    const int w    = tid >> 5;
    const int lane = tid & 31;

    if (blockIdx.x < STEP_BLOCKS) {
        // ---------------- recurrent step role ----------------
        {
            const float4* gh4 = (const float4*)g_h[pin];
            float4* s4 = (float4*)sbuf;
#pragma unroll
            for (int k = 0; k < 4; ++k) s4[tid + k * 128] = gh4[tid + k * 128];
        }
        __syncthreads();

        const int j = blockIdx.x;
        const float4* rp4 = (const float4*)(whh + ((size_t)w * I_DIM + j) * I_DIM);
        float acc = warp_sum(row_dot16_pipe(rp4, (const float4*)sbuf, lane));
        if (lane == 0) dots[w] = acc;
        __syncthreads();

        if (tid == 0) {
            const float* z = g_z + zoff;
            float gi = z[j]             + dots[0];
            float gf = z[I_DIM + j]     + dots[1];
            float gg = z[2 * I_DIM + j] + dots[2];
            float go = z[3 * I_DIM + j] + dots[3];
            float c  = sigmoidf_(gf) * g_c[pin][j] + sigmoidf_(gi) * tanhf(gg);
            float h  = sigmoidf_(go) * tanhf(c);
            g_c[pout][j] = c;
            g_h[pout][j] = h;
        }
    } else {
        // ---------------- z-precompute role ----------------
        const int zb = blockIdx.x - STEP_BLOCKS;

        if (mode == 0) {
            for (int k = tid; k < DM; k += 128)    sbuf[k]      = xvec[k];
            for (int k = tid; k < BBDIM; k += 128) sbuf[DM + k] = yvec[k];
            __syncthreads();

            const int r = (zb << 2) + w;           // 4 rows per block
            const float4* rp4 = (const float4*)(wz + (size_t)r * I_DIM);
            float acc = warp_sum(row_dot16_pipe(rp4, (const float4*)sbuf, lane));
            if (lane == 0) g_z[zout + r] = acc + bih[r] + bhh[r];
        } else {
            for (int k = tid; k < DM; k += 128) sbuf[k] = xvec[k];
            __syncthreads();

            const int rl = (zb << 2) + w;          // 0..1023
            const int g  = rl >> 8;
            const int jj = rl & 255;
            const int r  = g * I_DIM + DM + jj;    // actual WihF / z row
            const float4* rp4 = (const float4*)(wz + (size_t)r * DM);
            float acc = warp_sum(row_dot14_pipe(rp4, (const float4*)sbuf, lane));
            if (lane == 0) g_z[zout + r] = acc + bih[r] + bhh[r];
        }
    }
}

// ---------------------------------------------------------------------------
// Final step: only j in [1792, 2048) is needed. 256 blocks, one j each;
// warp w computes gate row w*2048 + j of WhhF. Writes d_out directly.
// ---------------------------------------------------------------------------
__global__ void __launch_bounds__(128, 8) final_step(
    const float* __restrict__ whhF,  // (8192, 2048)
    int pin,
    float* __restrict__ out)
{
    __shared__ float hs[I_DIM];
    __shared__ float dots[4];

    const int tid  = threadIdx.x;
    const int w    = tid >> 5;
    const int lane = tid & 31;

    {
        const float4* gh4 = (const float4*)g_h[pin];
        float4* s4 = (float4*)hs;
#pragma unroll
        for (int k = 0; k < 4; ++k) s4[tid + k * 128] = gh4[tid + k * 128];
    }
    __syncthreads();

    const int j = DM + blockIdx.x;                 // 1792 .. 2047
    const float4* rp4 = (const float4*)(whhF + ((size_t)w * I_DIM + j) * I_DIM);
    float acc = warp_sum(row_dot16_pipe(rp4, (const float4*)hs, lane));
    if (lane == 0) dots[w] = acc;
    __syncthreads();

    if (tid == 0) {
        const float* z = g_z + 5 * G_DIM;
        float gi = z[j]             + dots[0];
        float gf = z[I_DIM + j]     + dots[1];
        float gg = z[2 * I_DIM + j] + dots[2];
        float go = z[3 * I_DIM + j] + dots[3];
        float c  = sigmoidf_(gf) * g_c[pin][j] + sigmoidf_(gi) * tanhf(gg);
        float h  = sigmoidf_(go) * tanhf(c);
        out[blockIdx.x] = h;
    }
}

// ---------------------------------------------------------------------------
extern "C" void kernel_launch(void* const* d_in, const int* in_sizes, int n_in,
                              void* d_out, int out_size)
{
    const float* x    = (const float*)d_in[0];
    const float* y    = (const float*)d_in[1];
    const float* Wih5 = (const float*)d_in[2];
    const float* Whh5 = (const float*)d_in[3];
    const float* bih5 = (const float*)d_in[4];
    const float* bhh5 = (const float*)d_in[5];
    const float* WihF = (const float*)d_in[6];
    const float* WhhF = (const float*)d_in[7];
    const float* bihF = (const float*)d_in[8];
    const float* bhhF = (const float*)d_in[9];
    float* out = (float*)d_out;

    (void)in_sizes; (void)n_in; (void)out_size;

    const size_t WSTEP = (size_t)G_DIM * I_DIM;    // elems per (8192,2048) matrix

    // K0: z[0] and z[1] (134 MB, fully parallel)
    precompute_z01<<<2048, 256>>>(x, y, Wih5, bih5, bhh5);

    // step 0 (h0=c0=0: no Whh read)
    step0_kernel<<<(I_DIM + 255) / 256, 256>>>();

    // S1..S3: step t fused with z-precompute for cell t+1 (134 MB each)
    int pin = 0;
    for (int t = 1; t <= 3; ++t) {
        fused_step<<<STEP_BLOCKS + 2048, 128>>>(
            Whh5 + (size_t)t * WSTEP, t * G_DIM, pin, 1 - pin,
            Wih5 + (size_t)(t + 1) * WSTEP,
            x + (t + 1) * DM, y + (t + 1) * BBDIM,
            bih5 + (size_t)(t + 1) * G_DIM, bhh5 + (size_t)(t + 1) * G_DIM,
            (t + 1) * G_DIM, /*mode=*/0);
        pin = 1 - pin;
    }

    // S4: step 4 fused with the FINAL-cell z slice (67 + 7.3 MB)
    fused_step<<<STEP_BLOCKS + 256, 128>>>(
        Whh5 + (size_t)4 * WSTEP, 4 * G_DIM, pin, 1 - pin,
        WihF, x + 5 * DM, nullptr,
        bihF, bhhF, 5 * G_DIM, /*mode=*/1);
    pin = 1 - pin;

    // S5: final step, sliced to the 256 needed outputs (8.4 MB)
    final_step<<<256, 128>>>(WhhF, pin, out);
}